// round 13
// baseline (speedup 1.0000x reference)
#include <cuda_runtime.h>

// L1Distance via min identity, overhead-trimmed scalar version:
//   out[i][j] = max(rsA[i] + rsB[j] - 2 * sum_d min(x1[i,d], x2[j,d]), 0)
// Math: 1 FMNMX (alu) + 1 FADD (fma) per pair, scalar (no pack movs).
// - conflict-free staging: LDG.128 of 4 d's per row -> 4 STS.32, bank stride 1
// - unroll-8 inner loop, immediate-offset LDS (no per-load address IMADs)
// - 128x64 tile, 8x4/thread (~55 regs) -> 4 CTAs/SM, 512-CTA single wave

constexpr int D   = 64;
constexpr int TM  = 128;
constexpr int TN  = 64;
constexpr int DC  = 32;    // two d-chunks; smem ~25.6KB -> 4 CTAs/SM
constexpr int STA = 132;   // As stride (128 + 4 pad)
constexpr int STB = 68;    // Bs stride (64 + 4 pad)

__global__ __launch_bounds__(256, 4)
void l1dist_kernel(const float* __restrict__ x1, const float* __restrict__ x2,
                   float* __restrict__ out, int N2) {
    __shared__ __align__(16) float As[DC * STA];  // As[d][row] = x1[i0+row][dc+d]
    __shared__ __align__(16) float Bs[DC * STB];  // Bs[d][row] = x2[j0+row][dc+d]
    __shared__ float rsAs[TM];
    __shared__ float rsBs[TN];

    const int i0  = blockIdx.y * TM;
    const int j0  = blockIdx.x * TN;
    const int tid = (int)threadIdx.x;
    const int ty  = tid >> 4;     // 0..15: rows ty*4+{0..3}, 64+ty*4+{0..3}
    const int tx  = tid & 15;     // 0..15: cols tx*4+{0..3}
    const int w   = tid >> 5;     // warp 0..7
    const int l   = tid & 31;     // lane

    float acc[8][4];
#pragma unroll
    for (int m = 0; m < 8; m++)
#pragma unroll
        for (int n = 0; n < 4; n++) acc[m][n] = 0.0f;

    float rs = 0.0f;

    for (int dc = 0; dc < D; dc += DC) {
        // ---- stage A: row ra_ = (w&3)*32+l, 4 d's per LDG.128 ----
        // STS.32 addr = (d)*STA + row: lanes stride 1 word -> conflict-free.
        {
            int rowA = (w & 3) * 32 + l;
            const float* pA = x1 + (size_t)(i0 + rowA) * D + dc + (w >> 2) * 4;
#pragma unroll
            for (int it = 0; it < 4; it++) {
                float4 v = *(const float4*)(pA + it * 8);
                int d0 = (w >> 2) * 4 + it * 8;
                As[(d0 + 0) * STA + rowA] = v.x;
                As[(d0 + 1) * STA + rowA] = v.y;
                As[(d0 + 2) * STA + rowA] = v.z;
                As[(d0 + 3) * STA + rowA] = v.w;
            }
        }
        // ---- stage B: row rb_ = (w&1)*32+l, d0 = (w>>1)*8 + it*4 ----
        {
            int rowB = (w & 1) * 32 + l;
            const float* pB = x2 + (size_t)(j0 + rowB) * D + dc + (w >> 1) * 8;
#pragma unroll
            for (int it = 0; it < 2; it++) {
                float4 v = *(const float4*)(pB + it * 4);
                int d0 = (w >> 1) * 8 + it * 4;
                Bs[(d0 + 0) * STB + rowB] = v.x;
                Bs[(d0 + 1) * STB + rowB] = v.y;
                Bs[(d0 + 2) * STB + rowB] = v.z;
                Bs[(d0 + 3) * STB + rowB] = v.w;
            }
        }
        __syncthreads();

        // ---- partial rowsums (conflict-free: lanes stride 1) ----
        if (tid < TM) {
            const float* col = &As[tid];
#pragma unroll
            for (int d = 0; d < DC; d++) rs += col[d * STA];
        } else if (tid < TM + TN) {
            const float* col = &Bs[tid - TM];
#pragma unroll
            for (int d = 0; d < DC; d++) rs += col[d * STB];
        }

        // ---- compute: per d, 3 LDS.128 + 32 FMNMX + 32 FADD ----
        const float* asb = As + ty * 4;
        const float* bsb = Bs + tx * 4;
#pragma unroll 8
        for (int d = 0; d < DC; d++) {
            float4 a0 = *(const float4*)(asb + d * STA);
            float4 a1 = *(const float4*)(asb + d * STA + 64);
            float4 bv = *(const float4*)(bsb + d * STB);
            float ra[8] = {a0.x, a0.y, a0.z, a0.w, a1.x, a1.y, a1.z, a1.w};
#pragma unroll
            for (int m = 0; m < 8; m++) {
                acc[m][0] += fminf(ra[m], bv.x);
                acc[m][1] += fminf(ra[m], bv.y);
                acc[m][2] += fminf(ra[m], bv.z);
                acc[m][3] += fminf(ra[m], bv.w);
            }
        }
        __syncthreads();
    }

    // ---- publish rowsums ----
    if (tid < TM)            rsAs[tid] = rs;
    else if (tid < TM + TN)  rsBs[tid - TM] = rs;
    __syncthreads();

    float rsb[4] = {rsBs[tx * 4 + 0], rsBs[tx * 4 + 1],
                    rsBs[tx * 4 + 2], rsBs[tx * 4 + 3]};

    // ---- epilogue: out = max(rsA + rsB - 2*acc, 0) ----
#pragma unroll
    for (int m = 0; m < 8; m++) {
        int rloc = (m < 4) ? (ty * 4 + m) : (64 + ty * 4 + (m - 4));
        float rsa = rsAs[rloc];
        float* orow = out + (size_t)(i0 + rloc) * N2 + j0 + tx * 4;
        *(float4*)orow = make_float4(
            fmaxf(fmaf(-2.f, acc[m][0], rsa + rsb[0]), 0.f),
            fmaxf(fmaf(-2.f, acc[m][1], rsa + rsb[1]), 0.f),
            fmaxf(fmaf(-2.f, acc[m][2], rsa + rsb[2]), 0.f),
            fmaxf(fmaf(-2.f, acc[m][3], rsa + rsb[3]), 0.f));
    }
}

extern "C" void kernel_launch(void* const* d_in, const int* in_sizes, int n_in,
                              void* d_out, int out_size) {
    const float* x1 = (const float*)d_in[0];
    const float* x2 = (const float*)d_in[1];
    float* out = (float*)d_out;

    int N1 = in_sizes[0] / D;   // 2048
    int N2 = in_sizes[1] / D;   // 2048

    dim3 grid(N2 / TN, N1 / TM);   // 32 x 16 = 512 blocks (one wave @ 4/SM)
    l1dist_kernel<<<grid, 256>>>(x1, x2, out, N2);
}